// round 1
// baseline (speedup 1.0000x reference)
#include <cuda_runtime.h>
#include <cuda_bf16.h>

// Problem constants
#define B 8
#define S 2048
#define E 768
#define D 64
#define ROWS (B * S)   // 16384

// ---------------- scratch (no allocations allowed) ----------------
__device__ float g_q[ROWS * D];
__device__ float g_k[ROWS * D];
__device__ float g_v[ROWS * D];

// ================== Kernel 1: fused QKV projection ==================
// Y = X @ W + b for W in {Wq,Wk,Wv}.  M=16384, K=768, N=64.
// Block: 128 rows x 64 cols, 256 threads, 8x4 register tile per thread.
#define PM 128
#define PK 32
#define XSTR 36   // Xs row stride (floats): float4 stores phase-conflict-free

__global__ __launch_bounds__(256) void qkv_proj_kernel(
    const float* __restrict__ X,
    const float* __restrict__ Wq, const float* __restrict__ bq,
    const float* __restrict__ Wk, const float* __restrict__ bk,
    const float* __restrict__ Wv, const float* __restrict__ bv)
{
    __shared__ float Xs[PM * XSTR];   // [row][k]
    __shared__ float Ws[PK * 64];     // [k][col]

    const float* Wm; const float* bias; float* Y;
    if (blockIdx.y == 0)      { Wm = Wq; bias = bq; Y = g_q; }
    else if (blockIdx.y == 1) { Wm = Wk; bias = bk; Y = g_k; }
    else                      { Wm = Wv; bias = bv; Y = g_v; }

    const int tid = threadIdx.x;
    const int tr = tid >> 4;          // 0..15 -> rows tr*8 .. tr*8+7
    const int tc = tid & 15;          // cols tc + 16*j, j=0..3
    const int row0 = blockIdx.x * PM;

    float acc[8][4];
#pragma unroll
    for (int i = 0; i < 8; i++)
#pragma unroll
        for (int j = 0; j < 4; j++) acc[i][j] = 0.f;

    for (int k0 = 0; k0 < E; k0 += PK) {
        // load X tile: 128 rows x 32 k, float4
#pragma unroll
        for (int q = 0; q < 4; q++) {
            int idx = q * 256 + tid;          // 0..1023 float4 slots
            int row = idx >> 3;               // 8 float4 per row
            int kq  = idx & 7;
            float4 xv = *reinterpret_cast<const float4*>(
                &X[(size_t)(row0 + row) * E + k0 + kq * 4]);
            *reinterpret_cast<float4*>(&Xs[row * XSTR + kq * 4]) = xv;
        }
        // load W tile: 32 k x 64 cols, float4
#pragma unroll
        for (int q = 0; q < 2; q++) {
            int idx = q * 256 + tid;          // 0..511 float4 slots
            int wr = idx >> 4;                // 16 float4 per k-row
            int c4 = idx & 15;
            float4 wv = *reinterpret_cast<const float4*>(
                &Wm[(size_t)(k0 + wr) * D + c4 * 4]);
            *reinterpret_cast<float4*>(&Ws[wr * 64 + c4 * 4]) = wv;
        }
        __syncthreads();

#pragma unroll 8
        for (int kk = 0; kk < PK; kk++) {
            float a[8], w[4];
#pragma unroll
            for (int i = 0; i < 8; i++) a[i] = Xs[(tr * 8 + i) * XSTR + kk];
#pragma unroll
            for (int j = 0; j < 4; j++) w[j] = Ws[kk * 64 + tc + 16 * j];
#pragma unroll
            for (int i = 0; i < 8; i++)
#pragma unroll
                for (int j = 0; j < 4; j++)
                    acc[i][j] = fmaf(a[i], w[j], acc[i][j]);
        }
        __syncthreads();
    }

#pragma unroll
    for (int i = 0; i < 8; i++) {
        int row = row0 + tr * 8 + i;
#pragma unroll
        for (int j = 0; j < 4; j++) {
            int col = tc + 16 * j;
            Y[(size_t)row * D + col] = acc[i][j] + bias[col];
        }
    }
}

// ================== Kernel 2: causal flash attention ==================
// Per block: one (batch, 64-row Q tile). 256 threads, 4x4 register tiles.
#define BM 64
#define BN 64
#define KSTR 65   // Ks stride: scalar reads with lane-stride KSTR -> conflict-free
#define SSTR 68   // Ss stride: write lanes (dtc=1, dtr=4*68%32=16) conflict-free

// smem floats: Qs 64*64 + Ks 64*65 + Vs 64*64 + Ss 64*68 + m/l/sc 3*64
#define ATT_SMEM_FLOATS (64*64 + 64*KSTR + 64*64 + 64*SSTR + 3*64)
#define ATT_SMEM_BYTES (ATT_SMEM_FLOATS * 4)

__global__ __launch_bounds__(256) void attn_kernel(float* __restrict__ out)
{
    extern __shared__ float sm[];
    float* Qs  = sm;                       // [64][64]
    float* Ks  = Qs + 64 * 64;             // [64][KSTR]
    float* Vs  = Ks + 64 * KSTR;           // [64][64]
    float* Ss  = Vs + 64 * 64;             // [64][SSTR]
    float* m_s = Ss + 64 * SSTR;           // [64]
    float* l_s = m_s + 64;                 // [64]
    float* sc_s = l_s + 64;                // [64]

    const int tid = threadIdx.x;
    const int tr = tid >> 4;               // rows r0 = 4*tr .. +3
    const int tc = tid & 15;               // cols tc + 16*j
    const int r0 = tr * 4;
    const int qt = blockIdx.x;             // 0..31
    const int b  = blockIdx.y;             // 0..7
    const size_t base = (size_t)b * S * D;

    // ---- load Q tile (scaled by 1/sqrt(D)) ----
#pragma unroll
    for (int q = 0; q < 4; q++) {
        int idx = q * 256 + tid;           // 1024 float4 slots
        int row = idx >> 4;                // 16 float4 per row
        int c4  = idx & 15;
        float4 v = *reinterpret_cast<const float4*>(
            &g_q[base + (size_t)(qt * BM + row) * D + c4 * 4]);
        v.x *= 0.125f; v.y *= 0.125f; v.z *= 0.125f; v.w *= 0.125f;
        *reinterpret_cast<float4*>(&Qs[row * 64 + c4 * 4]) = v;
    }
    if (tid < 64) { m_s[tid] = -1e30f; l_s[tid] = 0.f; }

    float acc[4][4];
#pragma unroll
    for (int i = 0; i < 4; i++)
#pragma unroll
        for (int j = 0; j < 4; j++) acc[i][j] = 0.f;

    __syncthreads();

    for (int kt = 0; kt <= qt; kt++) {
        // ---- load K,V tiles ----
#pragma unroll
        for (int q = 0; q < 4; q++) {
            int idx = q * 256 + tid;
            int row = idx >> 4;
            int c4  = idx & 15;
            size_t g = base + (size_t)(kt * BN + row) * D + c4 * 4;
            float4 kv = *reinterpret_cast<const float4*>(&g_k[g]);
            Ks[row * KSTR + c4 * 4 + 0] = kv.x;
            Ks[row * KSTR + c4 * 4 + 1] = kv.y;
            Ks[row * KSTR + c4 * 4 + 2] = kv.z;
            Ks[row * KSTR + c4 * 4 + 3] = kv.w;
            float4 vv = *reinterpret_cast<const float4*>(&g_v[g]);
            *reinterpret_cast<float4*>(&Vs[row * 64 + c4 * 4]) = vv;
        }
        __syncthreads();

        // ---- phase A: S = Q K^T (scaled), causal mask on diagonal tile ----
        float s[4][4];
#pragma unroll
        for (int i = 0; i < 4; i++)
#pragma unroll
            for (int j = 0; j < 4; j++) s[i][j] = 0.f;

#pragma unroll 4
        for (int dd = 0; dd < D; dd++) {
            float a[4], kk[4];
#pragma unroll
            for (int i = 0; i < 4; i++) a[i] = Qs[(r0 + i) * 64 + dd];
#pragma unroll
            for (int j = 0; j < 4; j++) kk[j] = Ks[(tc + 16 * j) * KSTR + dd];
#pragma unroll
            for (int i = 0; i < 4; i++)
#pragma unroll
                for (int j = 0; j < 4; j++)
                    s[i][j] = fmaf(a[i], kk[j], s[i][j]);
        }
        const bool diag = (kt == qt);
#pragma unroll
        for (int i = 0; i < 4; i++) {
            int qr = r0 + i;  // local row; global offset identical for q & k tiles when diag
#pragma unroll
            for (int j = 0; j < 4; j++) {
                int kc = tc + 16 * j;
                float val = s[i][j];
                if (diag && kc > qr) val = -1e30f;
                Ss[qr * SSTR + kc] = val;
            }
        }
        __syncthreads();

        // ---- phase B: online softmax row pass (64 threads, 1 row each) ----
        if (tid < 64) {
            int r = tid;
            float mold = m_s[r];
            float mx = mold;
#pragma unroll 8
            for (int c = 0; c < BN; c++) mx = fmaxf(mx, Ss[r * SSTR + c]);
            float scale = __expf(mold - mx);
            float sum = 0.f;
#pragma unroll 4
            for (int c = 0; c < BN; c++) {
                float p = __expf(Ss[r * SSTR + c] - mx);
                Ss[r * SSTR + c] = p;
                sum += p;
            }
            m_s[r] = mx;
            l_s[r] = l_s[r] * scale + sum;
            sc_s[r] = scale;
        }
        __syncthreads();

        // ---- phase C: rescale accumulators, O += P V ----
#pragma unroll
        for (int i = 0; i < 4; i++) {
            float sc = sc_s[r0 + i];
#pragma unroll
            for (int j = 0; j < 4; j++) acc[i][j] *= sc;
        }
#pragma unroll 4
        for (int cc = 0; cc < BN; cc++) {
            float p[4], v[4];
#pragma unroll
            for (int i = 0; i < 4; i++) p[i] = Ss[(r0 + i) * SSTR + cc];
#pragma unroll
            for (int j = 0; j < 4; j++) v[j] = Vs[cc * 64 + tc + 16 * j];
#pragma unroll
            for (int i = 0; i < 4; i++)
#pragma unroll
                for (int j = 0; j < 4; j++)
                    acc[i][j] = fmaf(p[i], v[j], acc[i][j]);
        }
        __syncthreads();
    }

    // ---- epilogue: divide by row sum, write out ----
#pragma unroll
    for (int i = 0; i < 4; i++) {
        float inv = 1.0f / l_s[r0 + i];
        size_t row = base + (size_t)(qt * BM + r0 + i) * D;
#pragma unroll
        for (int j = 0; j < 4; j++) {
            out[row + tc + 16 * j] = acc[i][j] * inv;
        }
    }
}

// ================== launch ==================
extern "C" void kernel_launch(void* const* d_in, const int* in_sizes, int n_in,
                              void* d_out, int out_size)
{
    const float* X  = (const float*)d_in[0];
    const float* Wq = (const float*)d_in[1];
    const float* bq = (const float*)d_in[2];
    const float* Wk = (const float*)d_in[3];
    const float* bk = (const float*)d_in[4];
    const float* Wv = (const float*)d_in[5];
    const float* bv = (const float*)d_in[6];
    float* out = (float*)d_out;

    cudaFuncSetAttribute(attn_kernel,
                         cudaFuncAttributeMaxDynamicSharedMemorySize,
                         ATT_SMEM_BYTES);

    dim3 gProj(ROWS / PM, 3);
    qkv_proj_kernel<<<gProj, 256>>>(X, Wq, bq, Wk, bk, Wv, bv);

    dim3 gAtt(S / BM, B);
    attn_kernel<<<gAtt, 256, ATT_SMEM_BYTES>>>(out);
}

// round 4
// speedup vs baseline: 3.7086x; 3.7086x over previous
#include <cuda_runtime.h>
#include <cstdint>

// Problem constants
#define B 8
#define S 2048
#define E 768
#define D 64
#define ROWS (B * S)   // 16384

// ---------------- scratch (no allocations allowed) ----------------
__device__ float g_q[ROWS * D];
__device__ float g_k[ROWS * D];
__device__ float g_v[ROWS * D];
// attention partials: [b][Q(16)][chunk(<=8)][128 rows][64 cols]
__device__ float g_opart[8 * 16 * 8 * 128 * 64];
__device__ float g_lpart[8 * 16 * 8 * 128];

// ===================== mma.sync helpers =====================
__device__ __forceinline__ uint32_t f2tf(float x) {
    uint32_t r; asm("cvt.rna.tf32.f32 %0, %1;" : "=r"(r) : "f"(x)); return r;
}
// D(16x8,f32) += A(16x8,tf32,row) * B(8x8,tf32,col)
__device__ __forceinline__ void mma8(float* d, const uint32_t* a, uint32_t b0, uint32_t b1) {
    asm volatile("mma.sync.aligned.m16n8k8.row.col.f32.tf32.tf32.f32 "
        "{%0,%1,%2,%3}, {%4,%5,%6,%7}, {%8,%9}, {%0,%1,%2,%3};"
        : "+f"(d[0]), "+f"(d[1]), "+f"(d[2]), "+f"(d[3])
        : "r"(a[0]), "r"(a[1]), "r"(a[2]), "r"(a[3]), "r"(b0), "r"(b1));
}

// ================== Kernel 1: fused QKV projection (tf32 mma.sync) ==================
// Y = X @ W + b.  M=16384, K=768, N=64.  Block: 128x64, 256 thr (8 warps, each 32x32).
#define XSTR 20
#define WSTR 72

__global__ __launch_bounds__(256) void qkv_proj_kernel(
    const float* __restrict__ X,
    const float* __restrict__ Wq, const float* __restrict__ bq,
    const float* __restrict__ Wk, const float* __restrict__ bk,
    const float* __restrict__ Wv, const float* __restrict__ bv)
{
    __shared__ float Xs[128 * XSTR];
    __shared__ float Ws[16 * WSTR];

    const float* Wm; const float* bias; float* Y;
    if (blockIdx.y == 0)      { Wm = Wq; bias = bq; Y = g_q; }
    else if (blockIdx.y == 1) { Wm = Wk; bias = bk; Y = g_k; }
    else                      { Wm = Wv; bias = bv; Y = g_v; }

    const int tid = threadIdx.x;
    const int wid = tid >> 5, lane = tid & 31;
    const int g = lane >> 2, qd = lane & 3;
    const int wm = wid >> 1;            // 0..3: rows 32*wm
    const int wn = wid & 1;             // 0..1: cols 32*wn
    const int row0 = blockIdx.x * 128;

    float acc[2][4][4];
#pragma unroll
    for (int i = 0; i < 2; i++)
#pragma unroll
        for (int j = 0; j < 4; j++)
#pragma unroll
            for (int r = 0; r < 4; r++) acc[i][j][r] = 0.f;

    for (int k0 = 0; k0 < E; k0 += 16) {
        // X tile 128x16 -> Xs
#pragma unroll
        for (int q = 0; q < 2; q++) {
            int idx = q * 256 + tid;          // 512 float4 slots
            int r = idx >> 2, c4 = idx & 3;
            float4 x = *reinterpret_cast<const float4*>(&X[(size_t)(row0 + r) * E + k0 + c4 * 4]);
            *reinterpret_cast<float4*>(&Xs[r * XSTR + c4 * 4]) = x;
        }
        // W tile 16x64 -> Ws
        {
            int r = tid >> 4, c4 = tid & 15;
            float4 w = *reinterpret_cast<const float4*>(&Wm[(size_t)(k0 + r) * D + c4 * 4]);
            *reinterpret_cast<float4*>(&Ws[r * WSTR + c4 * 4]) = w;
        }
        __syncthreads();

#pragma unroll
        for (int ks = 0; ks < 2; ks++) {
            const int kb = ks * 8;
            uint32_t a[2][4];
#pragma unroll
            for (int i = 0; i < 2; i++) {
                int r = wm * 32 + i * 16 + g;
                a[i][0] = f2tf(Xs[r * XSTR + kb + qd]);
                a[i][1] = f2tf(Xs[(r + 8) * XSTR + kb + qd]);
                a[i][2] = f2tf(Xs[r * XSTR + kb + qd + 4]);
                a[i][3] = f2tf(Xs[(r + 8) * XSTR + kb + qd + 4]);
            }
#pragma unroll
            for (int j = 0; j < 4; j++) {
                int n = wn * 32 + j * 8 + g;
                uint32_t b0 = f2tf(Ws[(kb + qd) * WSTR + n]);
                uint32_t b1 = f2tf(Ws[(kb + qd + 4) * WSTR + n]);
#pragma unroll
                for (int i = 0; i < 2; i++) mma8(acc[i][j], a[i], b0, b1);
            }
        }
        __syncthreads();
    }

    // epilogue: add bias, store
#pragma unroll
    for (int i = 0; i < 2; i++) {
#pragma unroll
        for (int j = 0; j < 4; j++) {
            int col = wn * 32 + j * 8 + 2 * qd;
            float2 bb = *reinterpret_cast<const float2*>(&bias[col]);
            int r = row0 + wm * 32 + i * 16 + g;
            float2 v0 = make_float2(acc[i][j][0] + bb.x, acc[i][j][1] + bb.y);
            float2 v1 = make_float2(acc[i][j][2] + bb.x, acc[i][j][3] + bb.y);
            *reinterpret_cast<float2*>(&Y[(size_t)r * D + col]) = v0;
            *reinterpret_cast<float2*>(&Y[(size_t)(r + 8) * D + col]) = v1;
        }
    }
}

// ================== Kernel 2: tf32 mma.sync flash attention (fixed-max softmax) ==================
// Work unit: (batch b, 128-row q tile Q, chunk ch of up to 4 key-tiles of 64).
#define M0F 16.0f
#define PSTR 68   // Ps/Qs stride: A-frag lanes 4g+qd bijective -> conflict-free
#define KSTR 68   // Ks stride: B-frag lanes 4g+qd bijective
#define VSTR 72   // Vs stride: B-frag lanes 8qd+g bijective

#define PS_OFF 0
#define KS_OFF (128 * PSTR)
#define VS_OFF (KS_OFF + 64 * KSTR)
#define ATT_FLOATS (VS_OFF + 64 * VSTR)
#define ATT_SMEM_BYTES (ATT_FLOATS * 4)

__global__ __launch_bounds__(256) void attn_mma_kernel()
{
    extern __shared__ float sm[];
    float* Ps = sm + PS_OFF;     // also Q staging
    float* Ks = sm + KS_OFF;
    float* Vs = sm + VS_OFF;

    const int tid = threadIdx.x;
    const int wid = tid >> 5, lane = tid & 31;
    const int g = lane >> 2, qd = lane & 3;
    const int rbase = wid * 16;

    // ---- decode (b, Q, chunk) ----
    int c = blockIdx.x;
    int b = c / 72, u = c % 72;
    int pp = 0;
    while ((pp + 1) * (pp + 2) <= u) pp++;
    int v = u - pp * (pp + 1);
    int Q, ch;
    if (v < pp + 1) { Q = 2 * pp;     ch = v; }
    else            { Q = 2 * pp + 1; ch = v - (pp + 1); }
    const int q0 = Q * 128;
    const int nk = 2 * Q + 2;
    const int k_begin = ch * 4;
    const int k_end = min(k_begin + 4, nk);
    const size_t base = (size_t)b * S * D;

    // ---- stage Q (scaled by 1/8) into Ps, pull fragments to registers ----
    const float* qg = g_q + base + (size_t)q0 * D;
#pragma unroll
    for (int i = 0; i < 8; i++) {
        int idx = i * 256 + tid;           // 2048 float4 slots
        int r = idx >> 4, c4 = idx & 15;
        float4 x = *reinterpret_cast<const float4*>(qg + r * 64 + c4 * 4);
        x.x *= 0.125f; x.y *= 0.125f; x.z *= 0.125f; x.w *= 0.125f;
        *reinterpret_cast<float4*>(&Ps[r * PSTR + c4 * 4]) = x;
    }
    __syncthreads();

    uint32_t qa[8][4];
#pragma unroll
    for (int kk = 0; kk < 8; kk++) {
        int r = rbase + g;
        qa[kk][0] = f2tf(Ps[r * PSTR + kk * 8 + qd]);
        qa[kk][1] = f2tf(Ps[(r + 8) * PSTR + kk * 8 + qd]);
        qa[kk][2] = f2tf(Ps[r * PSTR + kk * 8 + qd + 4]);
        qa[kk][3] = f2tf(Ps[(r + 8) * PSTR + kk * 8 + qd + 4]);
    }

    float o[8][4];
#pragma unroll
    for (int t = 0; t < 8; t++)
#pragma unroll
        for (int r = 0; r < 4; r++) o[t][r] = 0.f;
    float l0 = 0.f, l1 = 0.f;

    const int qrow0 = q0 + rbase + g;
    const int qrow1 = qrow0 + 8;

    for (int kt = k_begin; kt < k_end; kt++) {
        const int k0 = kt * 64;
        __syncthreads();   // previous iteration's reads of Ks/Vs (and Q-frag reads on iter 1) done

        // ---- load K,V tiles (64x64 each) ----
        const float* kg = g_k + base + (size_t)k0 * D;
        const float* vg = g_v + base + (size_t)k0 * D;
#pragma unroll
        for (int i = 0; i < 4; i++) {
            int idx = i * 256 + tid;       // 1024 float4 slots
            int r = idx >> 4, c4 = idx & 15;
            float4 kv = *reinterpret_cast<const float4*>(kg + r * 64 + c4 * 4);
            *reinterpret_cast<float4*>(&Ks[r * KSTR + c4 * 4]) = kv;
            float4 vv = *reinterpret_cast<const float4*>(vg + r * 64 + c4 * 4);
            *reinterpret_cast<float4*>(&Vs[r * VSTR + c4 * 4]) = vv;
        }
        __syncthreads();

        // ---- S = Q K^T ----
        float s[8][4];
#pragma unroll
        for (int t = 0; t < 8; t++)
#pragma unroll
            for (int r = 0; r < 4; r++) s[t][r] = 0.f;
#pragma unroll
        for (int kk = 0; kk < 8; kk++) {
#pragma unroll
            for (int t = 0; t < 8; t++) {
                int key = t * 8 + g;                 // local key row in Ks
                uint32_t b0 = f2tf(Ks[key * KSTR + kk * 8 + qd]);
                uint32_t b1 = f2tf(Ks[key * KSTR + kk * 8 + qd + 4]);
                mma8(s[t], qa[kk], b0, b1);
            }
        }

        // ---- p = exp(s - M0) with causal mask; row sums; P -> Ps (warp-private rows) ----
#pragma unroll
        for (int t = 0; t < 8; t++) {
            int key = k0 + t * 8 + 2 * qd;
            float p0 = (key     <= qrow0) ? __expf(s[t][0] - M0F) : 0.f;
            float p1 = (key + 1 <= qrow0) ? __expf(s[t][1] - M0F) : 0.f;
            float p2 = (key     <= qrow1) ? __expf(s[t][2] - M0F) : 0.f;
            float p3 = (key + 1 <= qrow1) ? __expf(s[t][3] - M0F) : 0.f;
            l0 += p0 + p1;
            l1 += p2 + p3;
            *reinterpret_cast<float2*>(&Ps[(rbase + g) * PSTR + t * 8 + 2 * qd]) = make_float2(p0, p1);
            *reinterpret_cast<float2*>(&Ps[(rbase + g + 8) * PSTR + t * 8 + 2 * qd]) = make_float2(p2, p3);
        }
        __syncwarp();

        // ---- O += P V ----
#pragma unroll
        for (int kk = 0; kk < 8; kk++) {
            uint32_t pa[4];
            int r = rbase + g;
            pa[0] = f2tf(Ps[r * PSTR + kk * 8 + qd]);
            pa[1] = f2tf(Ps[(r + 8) * PSTR + kk * 8 + qd]);
            pa[2] = f2tf(Ps[r * PSTR + kk * 8 + qd + 4]);
            pa[3] = f2tf(Ps[(r + 8) * PSTR + kk * 8 + qd + 4]);
#pragma unroll
            for (int t = 0; t < 8; t++) {
                uint32_t b0 = f2tf(Vs[(kk * 8 + qd) * VSTR + t * 8 + g]);
                uint32_t b1 = f2tf(Vs[(kk * 8 + qd + 4) * VSTR + t * 8 + g]);
                mma8(o[t], pa, b0, b1);
            }
        }
        __syncwarp();
    }

    // ---- reduce l across quad lanes ----
    l0 += __shfl_xor_sync(0xFFFFFFFF, l0, 1);
    l0 += __shfl_xor_sync(0xFFFFFFFF, l0, 2);
    l1 += __shfl_xor_sync(0xFFFFFFFF, l1, 1);
    l1 += __shfl_xor_sync(0xFFFFFFFF, l1, 2);

    // ---- write partials ----
    const int prow_base = ((b * 16 + Q) * 8 + ch) * 128;
    const int r0 = rbase + g, r1 = rbase + g + 8;
#pragma unroll
    for (int t = 0; t < 8; t++) {
        int col = t * 8 + 2 * qd;
        *reinterpret_cast<float2*>(&g_opart[(size_t)(prow_base + r0) * 64 + col]) =
            make_float2(o[t][0], o[t][1]);
        *reinterpret_cast<float2*>(&g_opart[(size_t)(prow_base + r1) * 64 + col]) =
            make_float2(o[t][2], o[t][3]);
    }
    if (qd == 0) {
        g_lpart[prow_base + r0] = l0;
        g_lpart[prow_base + r1] = l1;
    }
}

// ================== Kernel 3: combine partials ==================
__global__ __launch_bounds__(256) void combine_kernel(float* __restrict__ out)
{
    const int wid = threadIdx.x >> 5, lane = threadIdx.x & 31;
    const int row = blockIdx.x * 8 + wid;          // 0..16383
    const int b = row >> 11;
    const int rr = row & 2047;
    const int Q = rr >> 7;
    const int r1 = rr & 127;
    const int nch = (Q >> 1) + 1;                  // chunks for this Q tile
    const int pbase = ((b * 16 + Q) * 8) * 128 + r1;

    float l = 0.f, o0 = 0.f, o1 = 0.f;
    for (int ch = 0; ch < nch; ch++) {
        int pr = pbase + ch * 128;
        l  += g_lpart[pr];
        o0 += g_opart[(size_t)pr * 64 + lane];
        o1 += g_opart[(size_t)pr * 64 + lane + 32];
    }
    float inv = 1.0f / l;
    out[(size_t)row * 64 + lane]      = o0 * inv;
    out[(size_t)row * 64 + lane + 32] = o1 * inv;
}

// ================== launch ==================
extern "C" void kernel_launch(void* const* d_in, const int* in_sizes, int n_in,
                              void* d_out, int out_size)
{
    const float* X  = (const float*)d_in[0];
    const float* Wq = (const float*)d_in[1];
    const float* bq = (const float*)d_in[2];
    const float* Wk = (const float*)d_in[3];
    const float* bk = (const float*)d_in[4];
    const float* Wv = (const float*)d_in[5];
    const float* bv = (const float*)d_in[6];
    float* out = (float*)d_out;

    cudaFuncSetAttribute(attn_mma_kernel,
                         cudaFuncAttributeMaxDynamicSharedMemorySize,
                         ATT_SMEM_BYTES);

    dim3 gProj(ROWS / 128, 3);
    qkv_proj_kernel<<<gProj, 256>>>(X, Wq, bq, Wk, bk, Wv, bv);

    attn_mma_kernel<<<576, 256, ATT_SMEM_BYTES>>>();

    combine_kernel<<<2048, 256>>>(out);
}

// round 6
// speedup vs baseline: 4.6711x; 1.2595x over previous
#include <cuda_runtime.h>
#include <cstdint>

// Problem constants
#define B 8
#define S 2048
#define E 768
#define D 64
#define ROWS (B * S)   // 16384

// ---------------- scratch (no allocations allowed) ----------------
__device__ float g_q[ROWS * D];
__device__ float g_k[ROWS * D];
__device__ float g_v[ROWS * D];
// attention partials: [b][Q(16)][chunk(<=8)][128 rows][64 cols]
__device__ float g_opart[8 * 16 * 8 * 128 * 64];
__device__ float g_lpart[8 * 16 * 8 * 128];

// ===================== mma.sync helpers =====================
__device__ __forceinline__ uint32_t f2tf(float x) {
    uint32_t r; asm("cvt.rna.tf32.f32 %0, %1;" : "=r"(r) : "f"(x)); return r;
}
// D(16x8,f32) += A(16x8,tf32,row) * B(8x8,tf32,col)
__device__ __forceinline__ void mma8(float* d, const uint32_t* a, uint32_t b0, uint32_t b1) {
    asm volatile("mma.sync.aligned.m16n8k8.row.col.f32.tf32.tf32.f32 "
        "{%0,%1,%2,%3}, {%4,%5,%6,%7}, {%8,%9}, {%0,%1,%2,%3};"
        : "+f"(d[0]), "+f"(d[1]), "+f"(d[2]), "+f"(d[3])
        : "r"(a[0]), "r"(a[1]), "r"(a[2]), "r"(a[3]), "r"(b0), "r"(b1));
}

// ================== Kernel 1: single-pass fused QKV projection (tf32 mma.sync) ==================
// Y[., 0:192] = X @ [Wq|Wk|Wv] + [bq|bk|bv].  M=16384, K=768, N=192.
// Block: 64 rows x 192 cols, 256 threads = 8 warps as 2(row) x 4(col); warp tile 32x48.
// smem holds PRE-CONVERTED tf32 bits -> zero cvt in the MMA loop.
#define PKT 32
#define PXS 36    // Xs stride (u32): A-frag banks 4g+qd bijective
#define PWS 200   // Ws stride (u32): B-frag banks 8qd+g bijective

__global__ __launch_bounds__(256) void qkv_proj_fused(
    const float* __restrict__ X,
    const float* __restrict__ Wq, const float* __restrict__ bq,
    const float* __restrict__ Wk, const float* __restrict__ bk,
    const float* __restrict__ Wv, const float* __restrict__ bv)
{
    __shared__ uint32_t Xs[64 * PXS];
    __shared__ uint32_t Ws[PKT * PWS];

    const int tid = threadIdx.x;
    const int wid = tid >> 5, lane = tid & 31;
    const int g = lane >> 2, qd = lane & 3;
    const int wrow = wid >> 2;          // 0..1 -> rows 32*wrow
    const int wcol = wid & 3;           // 0..3 -> cols 48*wcol
    const int row0 = blockIdx.x * 64;

    float acc[2][6][4];
#pragma unroll
    for (int i = 0; i < 2; i++)
#pragma unroll
        for (int j = 0; j < 6; j++)
#pragma unroll
            for (int r = 0; r < 4; r++) acc[i][j][r] = 0.f;

    const int wr_st = tid >> 3;         // staging row for W (0..31)
    const int wc8 = tid & 7;            // staging col8 for W

    for (int k0 = 0; k0 < E; k0 += PKT) {
        // ---- stage X tile 64x32 (cvt to tf32) ----
#pragma unroll
        for (int q = 0; q < 2; q++) {
            int idx = q * 256 + tid;     // 512 uint4 slots
            int r = idx >> 3, c4 = idx & 7;
            float4 x = *reinterpret_cast<const float4*>(&X[(size_t)(row0 + r) * E + k0 + c4 * 4]);
            uint4 u = make_uint4(f2tf(x.x), f2tf(x.y), f2tf(x.z), f2tf(x.w));
            *reinterpret_cast<uint4*>(&Xs[r * PXS + c4 * 4]) = u;
        }
        // ---- stage W tile 32x192 (Wq|Wk|Wv, cvt to tf32) ----
#pragma unroll
        for (int q = 0; q < 6; q++) {
            int cg = wc8 + 8 * q;        // 0..47 global col4
            int m = cg >> 4, c4in = cg & 15;
            const float* wp = (m == 0) ? Wq : ((m == 1) ? Wk : Wv);
            float4 w = *reinterpret_cast<const float4*>(&wp[(size_t)(k0 + wr_st) * D + c4in * 4]);
            uint4 u = make_uint4(f2tf(w.x), f2tf(w.y), f2tf(w.z), f2tf(w.w));
            *reinterpret_cast<uint4*>(&Ws[wr_st * PWS + cg * 4]) = u;
        }
        __syncthreads();

#pragma unroll
        for (int ks = 0; ks < 4; ks++) {
            const int kb = ks * 8;
            uint32_t a[2][4];
#pragma unroll
            for (int i = 0; i < 2; i++) {
                int r = wrow * 32 + i * 16 + g;
                a[i][0] = Xs[r * PXS + kb + qd];
                a[i][1] = Xs[(r + 8) * PXS + kb + qd];
                a[i][2] = Xs[r * PXS + kb + qd + 4];
                a[i][3] = Xs[(r + 8) * PXS + kb + qd + 4];
            }
#pragma unroll
            for (int j = 0; j < 6; j++) {
                int n = wcol * 48 + j * 8 + g;
                uint32_t b0 = Ws[(kb + qd) * PWS + n];
                uint32_t b1 = Ws[(kb + qd + 4) * PWS + n];
                mma8(acc[0][j], a[0], b0, b1);
                mma8(acc[1][j], a[1], b0, b1);
            }
        }
        __syncthreads();
    }

    // ---- epilogue: bias + store to g_q/g_k/g_v ----
#pragma unroll
    for (int j = 0; j < 6; j++) {
        int col = wcol * 48 + j * 8 + 2 * qd;    // 0..191
        int m = col >> 6, cin = col & 63;
        const float* bp = (m == 0) ? bq : ((m == 1) ? bk : bv);
        float* Y = (m == 0) ? g_q : ((m == 1) ? g_k : g_v);
        float2 bb = *reinterpret_cast<const float2*>(&bp[cin]);
#pragma unroll
        for (int i = 0; i < 2; i++) {
            int r = row0 + wrow * 32 + i * 16 + g;
            float2 v0 = make_float2(acc[i][j][0] + bb.x, acc[i][j][1] + bb.y);
            float2 v1 = make_float2(acc[i][j][2] + bb.x, acc[i][j][3] + bb.y);
            *reinterpret_cast<float2*>(&Y[(size_t)r * D + cin]) = v0;
            *reinterpret_cast<float2*>(&Y[(size_t)(r + 8) * D + cin]) = v1;
        }
    }
}

// ================== Kernel 2: tf32 mma.sync flash attention (fixed-max softmax) ==================
// Work unit: (batch b, 128-row q tile Q, chunk ch of up to 4 key-tiles of 64).
// All smem tiles hold tf32 bits (converted once at staging).
#define M0F 16.0f
#define PSTR 68
#define KSTR 68
#define VSTR 72

#define PS_OFF 0
#define KS_OFF (128 * PSTR)
#define VS_OFF (KS_OFF + 64 * KSTR)
#define ATT_U32 (VS_OFF + 64 * VSTR)
#define ATT_SMEM_BYTES (ATT_U32 * 4)

__global__ __launch_bounds__(256) void attn_mma_kernel()
{
    extern __shared__ uint32_t smu[];
    uint32_t* Ps = smu + PS_OFF;     // Q staging (float bits), then P (tf32 bits)
    uint32_t* Ks = smu + KS_OFF;     // tf32 bits
    uint32_t* Vs = smu + VS_OFF;     // tf32 bits

    const int tid = threadIdx.x;
    const int wid = tid >> 5, lane = tid & 31;
    const int g = lane >> 2, qd = lane & 3;
    const int rbase = wid * 16;

    // ---- decode (b, Q, chunk) ----
    int c = blockIdx.x;
    int b = c / 72, u = c % 72;
    int pp = 0;
    while ((pp + 1) * (pp + 2) <= u) pp++;
    int v = u - pp * (pp + 1);
    int Q, ch;
    if (v < pp + 1) { Q = 2 * pp;     ch = v; }
    else            { Q = 2 * pp + 1; ch = v - (pp + 1); }
    const int q0 = Q * 128;
    const int nk = 2 * Q + 2;
    const int k_begin = ch * 4;
    const int k_end = min(k_begin + 4, nk);
    const size_t base = (size_t)b * S * D;

    // ---- stage Q (scaled by 1/8, float bits), pull tf32 fragments to registers ----
    const float* qg = g_q + base + (size_t)q0 * D;
#pragma unroll
    for (int i = 0; i < 8; i++) {
        int idx = i * 256 + tid;
        int r = idx >> 4, c4 = idx & 15;
        float4 x = *reinterpret_cast<const float4*>(qg + r * 64 + c4 * 4);
        uint4 u4 = make_uint4(__float_as_uint(x.x * 0.125f), __float_as_uint(x.y * 0.125f),
                              __float_as_uint(x.z * 0.125f), __float_as_uint(x.w * 0.125f));
        *reinterpret_cast<uint4*>(&Ps[r * PSTR + c4 * 4]) = u4;
    }
    __syncthreads();

    uint32_t qa[8][4];
#pragma unroll
    for (int kk = 0; kk < 8; kk++) {
        int r = rbase + g;
        qa[kk][0] = f2tf(__uint_as_float(Ps[r * PSTR + kk * 8 + qd]));
        qa[kk][1] = f2tf(__uint_as_float(Ps[(r + 8) * PSTR + kk * 8 + qd]));
        qa[kk][2] = f2tf(__uint_as_float(Ps[r * PSTR + kk * 8 + qd + 4]));
        qa[kk][3] = f2tf(__uint_as_float(Ps[(r + 8) * PSTR + kk * 8 + qd + 4]));
    }

    float o[8][4];
#pragma unroll
    for (int t = 0; t < 8; t++)
#pragma unroll
        for (int r = 0; r < 4; r++) o[t][r] = 0.f;
    float l0 = 0.f, l1 = 0.f;

    const int qrow0 = q0 + rbase + g;
    const int qrow1 = qrow0 + 8;

    for (int kt = k_begin; kt < k_end; kt++) {
        const int k0 = kt * 64;
        __syncthreads();   // prior reads of Ks/Vs (and Q staging reads) complete

        // ---- stage K,V tiles (64x64 each), cvt to tf32 ----
        const float* kg = g_k + base + (size_t)k0 * D;
        const float* vg = g_v + base + (size_t)k0 * D;
#pragma unroll
        for (int i = 0; i < 4; i++) {
            int idx = i * 256 + tid;
            int r = idx >> 4, c4 = idx & 15;
            float4 kv = *reinterpret_cast<const float4*>(kg + r * 64 + c4 * 4);
            *reinterpret_cast<uint4*>(&Ks[r * KSTR + c4 * 4]) =
                make_uint4(f2tf(kv.x), f2tf(kv.y), f2tf(kv.z), f2tf(kv.w));
            float4 vv = *reinterpret_cast<const float4*>(vg + r * 64 + c4 * 4);
            *reinterpret_cast<uint4*>(&Vs[r * VSTR + c4 * 4]) =
                make_uint4(f2tf(vv.x), f2tf(vv.y), f2tf(vv.z), f2tf(vv.w));
        }
        __syncthreads();

        // ---- S = Q K^T (pure LDS + HMMA) ----
        float s[8][4];
#pragma unroll
        for (int t = 0; t < 8; t++)
#pragma unroll
            for (int r = 0; r < 4; r++) s[t][r] = 0.f;
#pragma unroll
        for (int kk = 0; kk < 8; kk++) {
#pragma unroll
            for (int t = 0; t < 8; t++) {
                int key = t * 8 + g;
                uint32_t b0 = Ks[key * KSTR + kk * 8 + qd];
                uint32_t b1 = Ks[key * KSTR + kk * 8 + qd + 4];
                mma8(s[t], qa[kk], b0, b1);
            }
        }

        // ---- p = exp(s - M0) with causal mask; row sums; P -> Ps as tf32 (warp-private rows) ----
#pragma unroll
        for (int t = 0; t < 8; t++) {
            int key = k0 + t * 8 + 2 * qd;
            float p0 = (key     <= qrow0) ? __expf(s[t][0] - M0F) : 0.f;
            float p1 = (key + 1 <= qrow0) ? __expf(s[t][1] - M0F) : 0.f;
            float p2 = (key     <= qrow1) ? __expf(s[t][2] - M0F) : 0.f;
            float p3 = (key + 1 <= qrow1) ? __expf(s[t][3] - M0F) : 0.f;
            l0 += p0 + p1;
            l1 += p2 + p3;
            *reinterpret_cast<uint2*>(&Ps[(rbase + g) * PSTR + t * 8 + 2 * qd]) =
                make_uint2(f2tf(p0), f2tf(p1));
            *reinterpret_cast<uint2*>(&Ps[(rbase + g + 8) * PSTR + t * 8 + 2 * qd]) =
                make_uint2(f2tf(p2), f2tf(p3));
        }
        __syncwarp();

        // ---- O += P V ----
#pragma unroll
        for (int kk = 0; kk < 8; kk++) {
            uint32_t pa[4];
            int r = rbase + g;
            pa[0] = Ps[r * PSTR + kk * 8 + qd];
            pa[1] = Ps[(r + 8) * PSTR + kk * 8 + qd];
            pa[2] = Ps[r * PSTR + kk * 8 + qd + 4];
            pa[3] = Ps[(r + 8) * PSTR + kk * 8 + qd + 4];
#pragma unroll
            for (int t = 0; t < 8; t++) {
                uint32_t b0 = Vs[(kk * 8 + qd) * VSTR + t * 8 + g];
                uint32_t b1 = Vs[(kk * 8 + qd + 4) * VSTR + t * 8 + g];
                mma8(o[t], pa, b0, b1);
            }
        }
        __syncwarp();
    }

    // ---- reduce l across quad lanes ----
    l0 += __shfl_xor_sync(0xFFFFFFFF, l0, 1);
    l0 += __shfl_xor_sync(0xFFFFFFFF, l0, 2);
    l1 += __shfl_xor_sync(0xFFFFFFFF, l1, 1);
    l1 += __shfl_xor_sync(0xFFFFFFFF, l1, 2);

    // ---- write partials ----
    const int prow_base = ((b * 16 + Q) * 8 + ch) * 128;
    const int r0 = rbase + g, r1 = rbase + g + 8;
#pragma unroll
    for (int t = 0; t < 8; t++) {
        int col = t * 8 + 2 * qd;
        *reinterpret_cast<float2*>(&g_opart[(size_t)(prow_base + r0) * 64 + col]) =
            make_float2(o[t][0], o[t][1]);
        *reinterpret_cast<float2*>(&g_opart[(size_t)(prow_base + r1) * 64 + col]) =
            make_float2(o[t][2], o[t][3]);
    }
    if (qd == 0) {
        g_lpart[prow_base + r0] = l0;
        g_lpart[prow_base + r1] = l1;
    }
}

// ================== Kernel 3: combine partials ==================
__global__ __launch_bounds__(256) void combine_kernel(float* __restrict__ out)
{
    const int wid = threadIdx.x >> 5, lane = threadIdx.x & 31;
    const int row = blockIdx.x * 8 + wid;          // 0..16383
    const int b = row >> 11;
    const int rr = row & 2047;
    const int Q = rr >> 7;
    const int r1 = rr & 127;
    const int nch = (Q >> 1) + 1;
    const int pbase = ((b * 16 + Q) * 8) * 128 + r1;

    float l = 0.f, o0 = 0.f, o1 = 0.f;
    for (int ch = 0; ch < nch; ch++) {
        int pr = pbase + ch * 128;
        l  += g_lpart[pr];
        o0 += g_opart[(size_t)pr * 64 + lane];
        o1 += g_opart[(size_t)pr * 64 + lane + 32];
    }
    float inv = 1.0f / l;
    out[(size_t)row * 64 + lane]      = o0 * inv;
    out[(size_t)row * 64 + lane + 32] = o1 * inv;
}

// ================== launch ==================
extern "C" void kernel_launch(void* const* d_in, const int* in_sizes, int n_in,
                              void* d_out, int out_size)
{
    const float* X  = (const float*)d_in[0];
    const float* Wq = (const float*)d_in[1];
    const float* bq = (const float*)d_in[2];
    const float* Wk = (const float*)d_in[3];
    const float* bk = (const float*)d_in[4];
    const float* Wv = (const float*)d_in[5];
    const float* bv = (const float*)d_in[6];
    float* out = (float*)d_out;

    cudaFuncSetAttribute(attn_mma_kernel,
                         cudaFuncAttributeMaxDynamicSharedMemorySize,
                         ATT_SMEM_BYTES);

    qkv_proj_fused<<<ROWS / 64, 256>>>(X, Wq, bq, Wk, bk, Wv, bv);

    attn_mma_kernel<<<576, 256, ATT_SMEM_BYTES>>>();

    combine_kernel<<<2048, 256>>>(out);
}

// round 7
// speedup vs baseline: 5.0078x; 1.0721x over previous
#include <cuda_runtime.h>
#include <cstdint>

// Problem constants
#define B 8
#define S 2048
#define E 768
#define D 64
#define ROWS (B * S)   // 16384

// ---------------- scratch (no allocations allowed) ----------------
__device__ float g_q[ROWS * D];      // tf32-rounded, pre-scaled by 1/8
__device__ float g_k[ROWS * D];      // tf32-rounded
__device__ float g_v[ROWS * D];      // tf32-rounded
__device__ uint32_t g_wt[E * 192];   // [Wq|Wk|Wv] as tf32 bits
// attention partials: [b][Q(16)][chunk(<=8)][128 rows][64 cols]
__device__ float g_opart[8 * 16 * 8 * 128 * 64];
__device__ float g_lpart[8 * 16 * 8 * 128];

// ===================== helpers =====================
__device__ __forceinline__ uint32_t f2tf(float x) {
    uint32_t r; asm("cvt.rna.tf32.f32 %0, %1;" : "=r"(r) : "f"(x)); return r;
}
__device__ __forceinline__ void mma8(float* d, const uint32_t* a, uint32_t b0, uint32_t b1) {
    asm volatile("mma.sync.aligned.m16n8k8.row.col.f32.tf32.tf32.f32 "
        "{%0,%1,%2,%3}, {%4,%5,%6,%7}, {%8,%9}, {%0,%1,%2,%3};"
        : "+f"(d[0]), "+f"(d[1]), "+f"(d[2]), "+f"(d[3])
        : "r"(a[0]), "r"(a[1]), "r"(a[2]), "r"(a[3]), "r"(b0), "r"(b1));
}
__device__ __forceinline__ uint32_t smem_u32(const void* p) {
    uint32_t a;
    asm("{ .reg .u64 t; cvta.to.shared.u64 t, %1; cvt.u32.u64 %0, t; }" : "=r"(a) : "l"(p));
    return a;
}
__device__ __forceinline__ void cpa16(uint32_t dst, const void* src) {
    asm volatile("cp.async.cg.shared.global [%0], [%1], 16;" :: "r"(dst), "l"(src));
}
#define CP_COMMIT() asm volatile("cp.async.commit_group;" ::: "memory")
#define CP_WAIT(N)  asm volatile("cp.async.wait_group %0;" :: "n"(N) : "memory")

// ================== Kernel 0: pre-convert W to tf32 bits ==================
__global__ __launch_bounds__(256) void prep_w(
    const float* __restrict__ Wq, const float* __restrict__ Wk, const float* __restrict__ Wv)
{
    int idx = blockIdx.x * 256 + threadIdx.x;   // 36864 float4 chunks
    int k = idx / 48, c4 = idx % 48;
    int m = c4 >> 4, cin = c4 & 15;
    const float* wp = (m == 0) ? Wq : ((m == 1) ? Wk : Wv);
    float4 w = *reinterpret_cast<const float4*>(&wp[(size_t)k * D + cin * 4]);
    uint4 u = make_uint4(f2tf(w.x), f2tf(w.y), f2tf(w.z), f2tf(w.w));
    *reinterpret_cast<uint4*>(&g_wt[(size_t)k * 192 + c4 * 4]) = u;
}

// ================== Kernel 1: fused QKV projection (cp.async double-buffered) ==================
// Y[., 0:192] = X @ [Wq|Wk|Wv] + bias.  Block: 64 rows x 192 cols, 8 warps (2x4), warp 32x48.
#define PKT 32
#define PXS 36    // Xs row stride u32 (144B, /16 ok)
#define PWS 200   // Ws row stride u32 (800B, /16 ok)
#define XBUF (64 * PXS)
#define WBUF (PKT * PWS)
#define PROJ_SMEM_BYTES ((2 * XBUF + 2 * WBUF) * 4)
#define NKT (E / PKT)   // 24

__global__ __launch_bounds__(256) void qkv_proj_fused(
    const float* __restrict__ X,
    const float* __restrict__ bq, const float* __restrict__ bk, const float* __restrict__ bv)
{
    extern __shared__ uint32_t smu[];
    uint32_t* Xs = smu;                  // [2][64*PXS] raw f32 bits
    uint32_t* Ws = smu + 2 * XBUF;       // [2][32*PWS] tf32 bits
    const uint32_t sb = smem_u32(smu);
    const uint32_t xb = sb;
    const uint32_t wb = sb + 2 * XBUF * 4;

    const int tid = threadIdx.x;
    const int wid = tid >> 5, lane = tid & 31;
    const int g = lane >> 2, qd = lane & 3;
    const int wrow = wid >> 2;          // 0..1
    const int wcol = wid & 3;           // 0..3
    const int row0 = blockIdx.x * 64;
    const int wr_st = tid >> 3;         // 0..31
    const int wc8 = tid & 7;

    float acc[2][6][4];
#pragma unroll
    for (int i = 0; i < 2; i++)
#pragma unroll
        for (int j = 0; j < 6; j++)
#pragma unroll
            for (int r = 0; r < 4; r++) acc[i][j][r] = 0.f;

    // ---- issue tile t into buffer bi ----
    auto issue = [&](int t, int bi) {
        const int k0 = t * PKT;
#pragma unroll
        for (int q = 0; q < 2; q++) {
            int idx = q * 256 + tid;             // 512 chunks
            int r = idx >> 3, c4 = idx & 7;
            cpa16(xb + (bi * XBUF + r * PXS + c4 * 4) * 4,
                  &X[(size_t)(row0 + r) * E + k0 + c4 * 4]);
        }
#pragma unroll
        for (int q = 0; q < 6; q++) {
            int cg = wc8 + 8 * q;                // 0..47
            cpa16(wb + (bi * WBUF + wr_st * PWS + cg * 4) * 4,
                  &g_wt[(size_t)(k0 + wr_st) * 192 + cg * 4]);
        }
        CP_COMMIT();
    };

    issue(0, 0);

    for (int t = 0; t < NKT; t++) {
        const int bi = t & 1;
        if (t + 1 < NKT) { issue(t + 1, bi ^ 1); CP_WAIT(1); }
        else             { CP_WAIT(0); }
        __syncthreads();

        const uint32_t* Xb = Xs + bi * XBUF;
        const uint32_t* Wb = Ws + bi * WBUF;
#pragma unroll
        for (int ks = 0; ks < 4; ks++) {
            const int kb = ks * 8;
            uint32_t a[2][4];
#pragma unroll
            for (int i = 0; i < 2; i++) {
                int r = wrow * 32 + i * 16 + g;
                a[i][0] = f2tf(__uint_as_float(Xb[r * PXS + kb + qd]));
                a[i][1] = f2tf(__uint_as_float(Xb[(r + 8) * PXS + kb + qd]));
                a[i][2] = f2tf(__uint_as_float(Xb[r * PXS + kb + qd + 4]));
                a[i][3] = f2tf(__uint_as_float(Xb[(r + 8) * PXS + kb + qd + 4]));
            }
#pragma unroll
            for (int j = 0; j < 6; j++) {
                int n = wcol * 48 + j * 8 + g;
                uint32_t b0 = Wb[(kb + qd) * PWS + n];
                uint32_t b1 = Wb[(kb + qd + 4) * PWS + n];
                mma8(acc[0][j], a[0], b0, b1);
                mma8(acc[1][j], a[1], b0, b1);
            }
        }
        __syncthreads();
    }

    // ---- epilogue: bias, (Q scale), tf32-round, store ----
#pragma unroll
    for (int j = 0; j < 6; j++) {
        int col = wcol * 48 + j * 8 + 2 * qd;    // 0..191
        int m = col >> 6, cin = col & 63;
        const float* bp = (m == 0) ? bq : ((m == 1) ? bk : bv);
        float* Y = (m == 0) ? g_q : ((m == 1) ? g_k : g_v);
        const float sc = (m == 0) ? 0.125f : 1.0f;
        float2 bb = *reinterpret_cast<const float2*>(&bp[cin]);
#pragma unroll
        for (int i = 0; i < 2; i++) {
            int r = row0 + wrow * 32 + i * 16 + g;
            float2 v0 = make_float2(__uint_as_float(f2tf((acc[i][j][0] + bb.x) * sc)),
                                    __uint_as_float(f2tf((acc[i][j][1] + bb.y) * sc)));
            float2 v1 = make_float2(__uint_as_float(f2tf((acc[i][j][2] + bb.x) * sc)),
                                    __uint_as_float(f2tf((acc[i][j][3] + bb.y) * sc)));
            *reinterpret_cast<float2*>(&Y[(size_t)r * D + cin]) = v0;
            *reinterpret_cast<float2*>(&Y[(size_t)(r + 8) * D + cin]) = v1;
        }
    }
}

// ================== Kernel 2: tf32 flash attention (cp.async, zero staging cvt) ==================
#define M0F 16.0f
#define PSTR 68
#define KSTR 68
#define VSTR 72
#define KBUF (64 * KSTR)
#define VBUF (64 * VSTR)
#define PS_U32 (128 * PSTR)
#define ATT_SMEM_BYTES ((PS_U32 + 2 * KBUF + 2 * VBUF) * 4)

__global__ __launch_bounds__(256) void attn_mma_kernel()
{
    extern __shared__ uint32_t smu[];
    uint32_t* Ps = smu;                       // Q (tf32 bits, pre-scaled), then P
    uint32_t* Ks = smu + PS_U32;              // [2][64*KSTR]
    uint32_t* Vs = smu + PS_U32 + 2 * KBUF;   // [2][64*VSTR]
    const uint32_t sb = smem_u32(smu);
    const uint32_t pb = sb;
    const uint32_t kb_ = sb + PS_U32 * 4;
    const uint32_t vb_ = sb + (PS_U32 + 2 * KBUF) * 4;

    const int tid = threadIdx.x;
    const int wid = tid >> 5, lane = tid & 31;
    const int g = lane >> 2, qd = lane & 3;
    const int rbase = wid * 16;

    // ---- decode (b, Q, chunk) ----
    int c = blockIdx.x;
    int b = c / 72, u = c % 72;
    int pp = 0;
    while ((pp + 1) * (pp + 2) <= u) pp++;
    int v = u - pp * (pp + 1);
    int Q, ch;
    if (v < pp + 1) { Q = 2 * pp;     ch = v; }
    else            { Q = 2 * pp + 1; ch = v - (pp + 1); }
    const int q0 = Q * 128;
    const int nk = 2 * Q + 2;
    const int k_begin = ch * 4;
    const int k_end = min(k_begin + 4, nk);
    const size_t base = (size_t)b * S * D;

    // ---- issue Q copy (group 0) ----
    const float* qg = g_q + base + (size_t)q0 * D;
#pragma unroll
    for (int i = 0; i < 8; i++) {
        int idx = i * 256 + tid;
        int r = idx >> 4, c4 = idx & 15;
        cpa16(pb + (r * PSTR + c4 * 4) * 4, qg + r * 64 + c4 * 4);
    }
    CP_COMMIT();

    // ---- issue K/V tile into buffer bi ----
    auto issue_kv = [&](int kt, int bi) {
        const float* kg = g_k + base + (size_t)kt * 64 * D;
        const float* vg = g_v + base + (size_t)kt * 64 * D;
#pragma unroll
        for (int i = 0; i < 4; i++) {
            int idx = i * 256 + tid;
            int r = idx >> 4, c4 = idx & 15;
            cpa16(kb_ + (bi * KBUF + r * KSTR + c4 * 4) * 4, kg + r * 64 + c4 * 4);
            cpa16(vb_ + (bi * VBUF + r * VSTR + c4 * 4) * 4, vg + r * 64 + c4 * 4);
        }
        CP_COMMIT();
    };

    issue_kv(k_begin, 0);
    CP_WAIT(1);          // Q group done
    __syncthreads();

    // ---- Q fragments: raw tf32 bits, no cvt ----
    uint32_t qa[8][4];
#pragma unroll
    for (int kk = 0; kk < 8; kk++) {
        int r = rbase + g;
        qa[kk][0] = Ps[r * PSTR + kk * 8 + qd];
        qa[kk][1] = Ps[(r + 8) * PSTR + kk * 8 + qd];
        qa[kk][2] = Ps[r * PSTR + kk * 8 + qd + 4];
        qa[kk][3] = Ps[(r + 8) * PSTR + kk * 8 + qd + 4];
    }

    float o[8][4];
#pragma unroll
    for (int t = 0; t < 8; t++)
#pragma unroll
        for (int r = 0; r < 4; r++) o[t][r] = 0.f;
    float l0 = 0.f, l1 = 0.f;

    const int qrow0 = q0 + rbase + g;
    const int qrow1 = qrow0 + 8;

    for (int kt = k_begin; kt < k_end; kt++) {
        const int k0 = kt * 64;
        const int bi = (kt - k_begin) & 1;
        if (kt + 1 < k_end) { issue_kv(kt + 1, bi ^ 1); CP_WAIT(1); }
        else                { CP_WAIT(0); }
        __syncthreads();

        const uint32_t* Kb = Ks + bi * KBUF;
        const uint32_t* Vb = Vs + bi * VBUF;

        // ---- S = Q K^T (raw tf32 bits) ----
        float s[8][4];
#pragma unroll
        for (int t = 0; t < 8; t++)
#pragma unroll
            for (int r = 0; r < 4; r++) s[t][r] = 0.f;
#pragma unroll
        for (int kk = 0; kk < 8; kk++) {
#pragma unroll
            for (int t = 0; t < 8; t++) {
                int key = t * 8 + g;
                uint32_t b0 = Kb[key * KSTR + kk * 8 + qd];
                uint32_t b1 = Kb[key * KSTR + kk * 8 + qd + 4];
                mma8(s[t], qa[kk], b0, b1);
            }
        }

        // ---- p = exp(s - M0), causal mask, row sums; P -> Ps as tf32 ----
#pragma unroll
        for (int t = 0; t < 8; t++) {
            int key = k0 + t * 8 + 2 * qd;
            float p0 = (key     <= qrow0) ? __expf(s[t][0] - M0F) : 0.f;
            float p1 = (key + 1 <= qrow0) ? __expf(s[t][1] - M0F) : 0.f;
            float p2 = (key     <= qrow1) ? __expf(s[t][2] - M0F) : 0.f;
            float p3 = (key + 1 <= qrow1) ? __expf(s[t][3] - M0F) : 0.f;
            l0 += p0 + p1;
            l1 += p2 + p3;
            *reinterpret_cast<uint2*>(&Ps[(rbase + g) * PSTR + t * 8 + 2 * qd]) =
                make_uint2(f2tf(p0), f2tf(p1));
            *reinterpret_cast<uint2*>(&Ps[(rbase + g + 8) * PSTR + t * 8 + 2 * qd]) =
                make_uint2(f2tf(p2), f2tf(p3));
        }
        __syncwarp();

        // ---- O += P V ----
#pragma unroll
        for (int kk = 0; kk < 8; kk++) {
            uint32_t pa[4];
            int r = rbase + g;
            pa[0] = Ps[r * PSTR + kk * 8 + qd];
            pa[1] = Ps[(r + 8) * PSTR + kk * 8 + qd];
            pa[2] = Ps[r * PSTR + kk * 8 + qd + 4];
            pa[3] = Ps[(r + 8) * PSTR + kk * 8 + qd + 4];
#pragma unroll
            for (int t = 0; t < 8; t++) {
                uint32_t b0 = Vb[(kk * 8 + qd) * VSTR + t * 8 + g];
                uint32_t b1 = Vb[(kk * 8 + qd + 4) * VSTR + t * 8 + g];
                mma8(o[t], pa, b0, b1);
            }
        }
        __syncthreads();   // buffer bi reads done before reissue
    }

    // ---- reduce l across quad lanes ----
    l0 += __shfl_xor_sync(0xFFFFFFFF, l0, 1);
    l0 += __shfl_xor_sync(0xFFFFFFFF, l0, 2);
    l1 += __shfl_xor_sync(0xFFFFFFFF, l1, 1);
    l1 += __shfl_xor_sync(0xFFFFFFFF, l1, 2);

    // ---- write partials ----
    const int prow_base = ((b * 16 + Q) * 8 + ch) * 128;
    const int r0 = rbase + g, r1 = rbase + g + 8;
#pragma unroll
    for (int t = 0; t < 8; t++) {
        int col = t * 8 + 2 * qd;
        *reinterpret_cast<float2*>(&g_opart[(size_t)(prow_base + r0) * 64 + col]) =
            make_float2(o[t][0], o[t][1]);
        *reinterpret_cast<float2*>(&g_opart[(size_t)(prow_base + r1) * 64 + col]) =
            make_float2(o[t][2], o[t][3]);
    }
    if (qd == 0) {
        g_lpart[prow_base + r0] = l0;
        g_lpart[prow_base + r1] = l1;
    }
}

// ================== Kernel 3: combine partials ==================
__global__ __launch_bounds__(256) void combine_kernel(float* __restrict__ out)
{
    const int wid = threadIdx.x >> 5, lane = threadIdx.x & 31;
    const int row = blockIdx.x * 8 + wid;          // 0..16383
    const int b = row >> 11;
    const int rr = row & 2047;
    const int Q = rr >> 7;
    const int r1 = rr & 127;
    const int nch = (Q >> 1) + 1;
    const int pbase = ((b * 16 + Q) * 8) * 128 + r1;

    float l = 0.f, o0 = 0.f, o1 = 0.f;
    for (int ch = 0; ch < nch; ch++) {
        int pr = pbase + ch * 128;
        l  += g_lpart[pr];
        o0 += g_opart[(size_t)pr * 64 + lane];
        o1 += g_opart[(size_t)pr * 64 + lane + 32];
    }
    float inv = 1.0f / l;
    out[(size_t)row * 64 + lane]      = o0 * inv;
    out[(size_t)row * 64 + lane + 32] = o1 * inv;
}

// ================== launch ==================
extern "C" void kernel_launch(void* const* d_in, const int* in_sizes, int n_in,
                              void* d_out, int out_size)
{
    const float* X  = (const float*)d_in[0];
    const float* Wq = (const float*)d_in[1];
    const float* bq = (const float*)d_in[2];
    const float* Wk = (const float*)d_in[3];
    const float* bk = (const float*)d_in[4];
    const float* Wv = (const float*)d_in[5];
    const float* bv = (const float*)d_in[6];
    float* out = (float*)d_out;

    cudaFuncSetAttribute(qkv_proj_fused,
                         cudaFuncAttributeMaxDynamicSharedMemorySize, PROJ_SMEM_BYTES);
    cudaFuncSetAttribute(attn_mma_kernel,
                         cudaFuncAttributeMaxDynamicSharedMemorySize, ATT_SMEM_BYTES);

    prep_w<<<144, 256>>>(Wq, Wk, Wv);
    qkv_proj_fused<<<ROWS / 64, 256, PROJ_SMEM_BYTES>>>(X, bq, bk, bv);
    attn_mma_kernel<<<576, 256, ATT_SMEM_BYTES>>>();
    combine_kernel<<<2048, 256>>>(out);
}